// round 15
// baseline (speedup 1.0000x reference)
#include <cuda_runtime.h>

// Problem constants (fixed by the reference):
//   B=32768, LMAX=24, M=10, D=300, V=36
#define BB    32768
#define LMAXC 24
#define MC    10
#define D4C   75          // D / 4 float4s per (b,m) row

// One warp per (b,m) output row. 8 warps / 256-thread block.
// grid = B*M/8 = 40960 blocks (exact). Champion R6 structure; the single
// change vs the 57.1us kernel is __stwt (write-through) stores instead of
// __stcs, removing L2 allocation for the 393MB write-once output stream.
__global__ __launch_bounds__(256)
void word_emb_kernel(const float4* __restrict__ emb,     // [36, 75] float4
                     const float4* __restrict__ pad,     // [75] float4
                     const int*    __restrict__ tokens,  // [B, 24]
                     const int*    __restrict__ lengths, // [B]
                     float4*       __restrict__ out)     // [B*10, 75] float4
{
    const int gwarp = (blockIdx.x * 256 + threadIdx.x) >> 5;  // 0 .. B*M-1
    const int lane  = threadIdx.x & 31;
    const int b     = gwarp / MC;
    const int m     = gwarp - b * MC;

    const int L = __ldg(lengths + b);                  // warp-uniform broadcast
    float4* orow = out + (long long)gwarp * D4C;

    if (L < MC) {
        // ---- padding branch: row m is either embedding of token m or pad vec
        const float4* src;
        if (m < L) {
            const int t = __ldg(tokens + b * LMAXC + m);
            src = emb + t * D4C;
        } else {
            src = pad;
        }
        const float4 v0 = src[lane];
        const float4 v1 = src[lane + 32];
        __stwt(orow + lane,      v0);
        __stwt(orow + lane + 32, v1);
        if (lane < D4C - 64) {
            __stwt(orow + lane + 64, src[lane + 64]);
        }
    } else {
        // ---- interpolate branch: src = m*(L-1)/9, align_corners (fp32 as ref)
        const float pos = (float)(m * (L - 1)) / 9.0f;
        const int   lo  = (int)pos;
        const int   hi  = min(lo + 1, L - 1);
        const float w   = pos - (float)lo;
        const float wm  = 1.0f - w;

        const int tlo = __ldg(tokens + b * LMAXC + lo);
        const int thi = __ldg(tokens + b * LMAXC + hi);
        const float4* ea = emb + tlo * D4C;
        const float4* eb = emb + thi * D4C;

        // issue all loads up front for MLP
        const float4 a0 = ea[lane];
        const float4 b0 = eb[lane];
        const float4 a1 = ea[lane + 32];
        const float4 b1 = eb[lane + 32];

        float4 o0, o1;
        o0.x = a0.x * wm + b0.x * w;  o0.y = a0.y * wm + b0.y * w;
        o0.z = a0.z * wm + b0.z * w;  o0.w = a0.w * wm + b0.w * w;
        o1.x = a1.x * wm + b1.x * w;  o1.y = a1.y * wm + b1.y * w;
        o1.z = a1.z * wm + b1.z * w;  o1.w = a1.w * wm + b1.w * w;
        __stwt(orow + lane,      o0);
        __stwt(orow + lane + 32, o1);

        if (lane < D4C - 64) {
            const float4 a2 = ea[lane + 64];
            const float4 b2 = eb[lane + 64];
            float4 o2;
            o2.x = a2.x * wm + b2.x * w;  o2.y = a2.y * wm + b2.y * w;
            o2.z = a2.z * wm + b2.z * w;  o2.w = a2.w * wm + b2.w * w;
            __stwt(orow + lane + 64, o2);
        }
    }
}

extern "C" void kernel_launch(void* const* d_in, const int* in_sizes, int n_in,
                              void* d_out, int out_size)
{
    const float4* emb     = (const float4*)d_in[0];  // emb_table [36, 300] f32
    const float4* pad     = (const float4*)d_in[1];  // pad_table [1, 300] f32
    const int*    tokens  = (const int*)d_in[2];     // tokens [32768, 24] i32
    const int*    lengths = (const int*)d_in[3];     // lengths [32768] i32
    float4*       out     = (float4*)d_out;          // [32768, 10, 300] f32

    const int nwarps = BB * MC;                      // 327,680 warps
    const int blocks = nwarps / 8;                   // 40,960 blocks of 256 (exact)
    word_emb_kernel<<<blocks, 256>>>(emb, pad, tokens, lengths, out);
}

// round 16
// speedup vs baseline: 1.3354x; 1.3354x over previous
#include <cuda_runtime.h>

// Problem constants (fixed by the reference):
//   B=32768, LMAX=24, M=10, D=300, V=36
#define BB    32768
#define LMAXC 24
#define MC    10
#define D4C   75          // D / 4 float4s per (b,m) row

// CHAMPION (57.1us). One warp per (b,m) output row; 8 warps / 256-thread
// block; grid = B*M/8 = 40960 (exact). Warp-uniform scalar work,
// front-batched LDG.128 payload loads, and evict-first (__stcs) stores —
// measured optimal store policy: lines stay in L2 just long enough to merge
// the 16B-misaligned row-edge sectors with the adjacent warp's stores, then
// evict without polluting the embedding-table read path.
__global__ __launch_bounds__(256)
void word_emb_kernel(const float4* __restrict__ emb,     // [36, 75] float4
                     const float4* __restrict__ pad,     // [75] float4
                     const int*    __restrict__ tokens,  // [B, 24]
                     const int*    __restrict__ lengths, // [B]
                     float4*       __restrict__ out)     // [B*10, 75] float4
{
    const int gwarp = (blockIdx.x * 256 + threadIdx.x) >> 5;  // 0 .. B*M-1
    const int lane  = threadIdx.x & 31;
    const int b     = gwarp / MC;
    const int m     = gwarp - b * MC;

    const int L = __ldg(lengths + b);                  // warp-uniform broadcast
    float4* orow = out + (long long)gwarp * D4C;

    if (L < MC) {
        // ---- padding branch: row m is either embedding of token m or pad vec
        const float4* src;
        if (m < L) {
            const int t = __ldg(tokens + b * LMAXC + m);
            src = emb + t * D4C;
        } else {
            src = pad;
        }
        const float4 v0 = src[lane];
        const float4 v1 = src[lane + 32];
        __stcs(orow + lane,      v0);
        __stcs(orow + lane + 32, v1);
        if (lane < D4C - 64) {
            __stcs(orow + lane + 64, src[lane + 64]);
        }
    } else {
        // ---- interpolate branch: src = m*(L-1)/9, align_corners (fp32 as ref)
        const float pos = (float)(m * (L - 1)) / 9.0f;
        const int   lo  = (int)pos;
        const int   hi  = min(lo + 1, L - 1);
        const float w   = pos - (float)lo;
        const float wm  = 1.0f - w;

        const int tlo = __ldg(tokens + b * LMAXC + lo);
        const int thi = __ldg(tokens + b * LMAXC + hi);
        const float4* ea = emb + tlo * D4C;
        const float4* eb = emb + thi * D4C;

        // issue all loads up front for MLP
        const float4 a0 = ea[lane];
        const float4 b0 = eb[lane];
        const float4 a1 = ea[lane + 32];
        const float4 b1 = eb[lane + 32];

        float4 o0, o1;
        o0.x = a0.x * wm + b0.x * w;  o0.y = a0.y * wm + b0.y * w;
        o0.z = a0.z * wm + b0.z * w;  o0.w = a0.w * wm + b0.w * w;
        o1.x = a1.x * wm + b1.x * w;  o1.y = a1.y * wm + b1.y * w;
        o1.z = a1.z * wm + b1.z * w;  o1.w = a1.w * wm + b1.w * w;
        __stcs(orow + lane,      o0);
        __stcs(orow + lane + 32, o1);

        if (lane < D4C - 64) {
            const float4 a2 = ea[lane + 64];
            const float4 b2 = eb[lane + 64];
            float4 o2;
            o2.x = a2.x * wm + b2.x * w;  o2.y = a2.y * wm + b2.y * w;
            o2.z = a2.z * wm + b2.z * w;  o2.w = a2.w * wm + b2.w * w;
            __stcs(orow + lane + 64, o2);
        }
    }
}

extern "C" void kernel_launch(void* const* d_in, const int* in_sizes, int n_in,
                              void* d_out, int out_size)
{
    const float4* emb     = (const float4*)d_in[0];  // emb_table [36, 300] f32
    const float4* pad     = (const float4*)d_in[1];  // pad_table [1, 300] f32
    const int*    tokens  = (const int*)d_in[2];     // tokens [32768, 24] i32
    const int*    lengths = (const int*)d_in[3];     // lengths [32768] i32
    float4*       out     = (float4*)d_out;          // [32768, 10, 300] f32

    const int nwarps = BB * MC;                      // 327,680 warps
    const int blocks = nwarps / 8;                   // 40,960 blocks of 256 (exact)
    word_emb_kernel<<<blocks, 256>>>(emb, pad, tokens, lengths, out);
}